// round 2
// baseline (speedup 1.0000x reference)
#include <cuda_runtime.h>
#include <math.h>

#define H   16
#define BB  4
#define NN  512
#define DD  1024
#define DK  64
#define DR  128
#define BH  (BB*H)   // 64

// ---------------- scratch (static device globals; no allocation) ----------------
__device__ float g_qh  [BH*NN*DK];        // [bh][n][d]     8 MB
__device__ float g_khT [BH*DK*NN];        // [bh][d][n]     8 MB
__device__ float g_vh  [BH*NN*DK];        // [bh][n][d]     8 MB
__device__ float g_qtil[BH*NN*DR];        // [bh][n][e]    16 MB
__device__ float g_score[BH*NN*NN];       // [bh][m][n]    64 MB (score -> att in place)
__device__ float g_u   [BH*NN*DR];        // [bh][m][e]    16 MB
__device__ float g_av  [BH*NN*DK];        // [bh][m][d]     8 MB
__device__ float g_val [BB*NN*DD];        // [b][m][h*64+d] 8 MB
__device__ float g_WrkT[DK*DR];           // [d][e]

// ---------------- generic fp32 SGEMM: C = alpha*A@B (+bias), layout epilogues ----
// BM=BN=128, BK=8, 256 threads, 8x8 per thread. Batched via blockIdx.z + strides.
// mode 0: C[z*sC + r*N + c]
// mode 1: HEAD  : qh/vh layout  [((b*16+h)*512+n)*64 + d]
// mode 2: HEADT : khT layout    [((b*16+h)*64+d)*512 + n]
__global__ __launch_bounds__(256) void sgemm_k(
    const float* __restrict__ A, const float* __restrict__ B,
    const float* __restrict__ bias, float* __restrict__ C,
    int M, int N, int K, float alpha,
    long long sA, long long sB, long long sC, int mode)
{
    __shared__ float As[8][128];
    __shared__ float Bs[8][128];
    int tid = threadIdx.x;
    int tx = tid & 15, ty = tid >> 4;
    int aRow = tid >> 1, aCol = (tid & 1) << 2;
    int bRow = tid >> 5, bCol = (tid & 31) << 2;

    const float* Ag = A + blockIdx.z * sA + (long long)(blockIdx.y * 128 + aRow) * K + aCol;
    int gcol = blockIdx.x * 128 + bCol;
    const float* Bg = B + blockIdx.z * sB + (long long)bRow * N + gcol;
    bool bValid = gcol < N;

    float acc[8][8];
    #pragma unroll
    for (int i = 0; i < 8; i++)
        #pragma unroll
        for (int j = 0; j < 8; j++) acc[i][j] = 0.f;

    for (int k0 = 0; k0 < K; k0 += 8) {
        float4 a4 = *(const float4*)(Ag + k0);
        As[aCol + 0][aRow] = a4.x;
        As[aCol + 1][aRow] = a4.y;
        As[aCol + 2][aRow] = a4.z;
        As[aCol + 3][aRow] = a4.w;
        float4 b4 = bValid ? *(const float4*)(Bg + (long long)k0 * N)
                           : make_float4(0.f, 0.f, 0.f, 0.f);
        *(float4*)&Bs[bRow][bCol] = b4;
        __syncthreads();
        #pragma unroll
        for (int kk = 0; kk < 8; kk++) {
            float4 a0 = *(const float4*)&As[kk][ty * 8];
            float4 a1 = *(const float4*)&As[kk][ty * 8 + 4];
            float4 b0 = *(const float4*)&Bs[kk][tx * 8];
            float4 b1 = *(const float4*)&Bs[kk][tx * 8 + 4];
            float am[8] = {a0.x, a0.y, a0.z, a0.w, a1.x, a1.y, a1.z, a1.w};
            float bn[8] = {b0.x, b0.y, b0.z, b0.w, b1.x, b1.y, b1.z, b1.w};
            #pragma unroll
            for (int i = 0; i < 8; i++)
                #pragma unroll
                for (int j = 0; j < 8; j++) acc[i][j] += am[i] * bn[j];
        }
        __syncthreads();
    }

    int rowBase = blockIdx.y * 128 + ty * 8;
    int colBase = blockIdx.x * 128 + tx * 8;
    #pragma unroll
    for (int i = 0; i < 8; i++) {
        int r = rowBase + i;
        #pragma unroll
        for (int j = 0; j < 8; j++) {
            int c = colBase + j;
            if (c < N) {
                float vv = acc[i][j] * alpha;
                if (bias) vv += bias[c];
                long long idx;
                if (mode == 0) {
                    idx = blockIdx.z * sC + (long long)r * N + c;
                } else {
                    int b = r >> 9, n = r & 511, h = c >> 6, d = c & 63;
                    if (mode == 1) idx = ((long long)(b * H + h) * NN + n) * DK + d;
                    else           idx = ((long long)(b * H + h) * DK + d) * NN + n;
                }
                C[idx] = vv;
            }
        }
    }
}

// ---------------- Wrk transpose: WrkT[d][e] = Wrk[e][d] ----------------
__global__ void transp_wrk(const float* __restrict__ Wrk)
{
    int i = blockIdx.x * 256 + threadIdx.x;
    if (i < DR * DK) {
        int e = i >> 6, d = i & 63;
        g_WrkT[d * DR + e] = Wrk[i];
    }
}

// ---------------- fused attention per (b, m) ----------------
// In : g_score holds scale*qh@kh^T rows for this (b,m); g_qtil; r_k, r_v raw.
// Out: g_score rows overwritten with normalized att; g_u[bh][m][e].
#define CHUNK_PAD 132
#define ATTN_SMEM ((H*NN + H*DR + 16*CHUNK_PAD) * 4)   // 49408 B

__global__ __launch_bounds__(256) void attn_k(
    const float* __restrict__ rk, const float* __restrict__ rv)
{
    extern __shared__ float sm[];
    float* s_score = sm;                  // 16*512
    float* s_qtil  = sm + H * NN;         // 16*128
    float* s_chunk = s_qtil + H * DR;     // 16*132 (padded)

    int tid = threadIdx.x;
    int m = blockIdx.x, b = blockIdx.y;

    // load q~ rows and score rows for this (b, m)
    for (int i = tid; i < H * DR; i += 256) {
        int h = i >> 7, e = i & 127;
        s_qtil[i] = g_qtil[((long long)(b * H + h) * NN + m) * DR + e];
    }
    for (int i = tid; i < H * NN; i += 256) {
        int h = i >> 9, n = i & 511;
        s_score[i] = g_score[((long long)(b * H + h) * NN + m) * NN + n];
    }
    __syncthreads();

    // ---- phase 1: relation-key bias. score[h][n] += q~[h,:] . r_k[b,m,n,:]
    const float* rkb = rk + ((long long)(b * NN + m)) * NN * DR;
    int hh = tid >> 4, nl = tid & 15;
    for (int nc = 0; nc < NN / 16; nc++) {
        // cooperative load of 16x128 chunk (float4, coalesced)
        const float4* src = (const float4*)(rkb + (long long)nc * 2048);
        #pragma unroll
        for (int j = 0; j < 2; j++) {
            int g = tid + j * 256;           // float4 index 0..511
            int cn = g >> 5, ce = (g & 31) << 2;
            *(float4*)&s_chunk[cn * CHUNK_PAD + ce] = src[g];
        }
        __syncthreads();
        float acc = 0.f;
        const float4* q4 = (const float4*)(s_qtil + hh * DR);
        const float4* c4 = (const float4*)(s_chunk + nl * CHUNK_PAD);
        #pragma unroll
        for (int e4 = 0; e4 < DR / 4; e4++) {
            float4 a = q4[e4], r = c4[e4];
            acc += a.x * r.x + a.y * r.y + a.z * r.z + a.w * r.w;
        }
        s_score[hh * NN + nc * 16 + nl] += acc;
        __syncthreads();
    }

    // ---- phase 2: softmax per head row; write att back to gmem for av GEMM
    int w = tid >> 5, lane = tid & 31;
    for (int h = w * 2; h < w * 2 + 2; h++) {
        float* row = s_score + h * NN;
        float mx = -1e30f;
        for (int n = lane; n < NN; n += 32) mx = fmaxf(mx, row[n]);
        #pragma unroll
        for (int o = 16; o; o >>= 1) mx = fmaxf(mx, __shfl_xor_sync(0xffffffffu, mx, o));
        float sum = 0.f;
        for (int n = lane; n < NN; n += 32) {
            float e = __expf(row[n] - mx);
            row[n] = e;
            sum += e;
        }
        #pragma unroll
        for (int o = 16; o; o >>= 1) sum += __shfl_xor_sync(0xffffffffu, sum, o);
        float inv = 1.0f / sum;
        float* gatt = g_score + ((long long)(b * H + h) * NN + m) * NN;
        for (int n = lane; n < NN; n += 32) {
            float a = row[n] * inv;
            row[n] = a;
            gatt[n] = a;
        }
    }
    __syncthreads();

    // ---- phase 3: u[h][e] = sum_n att[h][n] * r_v[b,m,n,e]
    const float* rvb = rv + ((long long)(b * NN + m)) * NN * DR;
    int e = tid & 127, hg = tid >> 7;     // hg in {0,1}: heads hg*8 .. hg*8+7
    float ur[8];
    #pragma unroll
    for (int j = 0; j < 8; j++) ur[j] = 0.f;

    for (int nc = 0; nc < NN / 16; nc++) {
        const float4* src = (const float4*)(rvb + (long long)nc * 2048);
        #pragma unroll
        for (int j = 0; j < 2; j++) {
            int g = tid + j * 256;
            int cn = g >> 5, ce = (g & 31) << 2;
            *(float4*)&s_chunk[cn * CHUNK_PAD + ce] = src[g];
        }
        __syncthreads();
        #pragma unroll
        for (int nl = 0; nl < 16; nl++) {
            int n = nc * 16 + nl;
            float rvv = s_chunk[nl * CHUNK_PAD + e];
            #pragma unroll
            for (int j = 0; j < 8; j++)
                ur[j] += s_score[(hg * 8 + j) * NN + n] * rvv;
        }
        __syncthreads();
    }
    #pragma unroll
    for (int j = 0; j < 8; j++)
        g_u[((long long)(b * H + hg * 8 + j) * NN + m) * DR + e] = ur[j];
}

// ---------------- val assembly: val[b,m,h*64+d] = av + u@Wrv + brv ----------------
__global__ __launch_bounds__(256) void assemble_k(
    const float* __restrict__ Wrv, const float* __restrict__ brv)
{
    __shared__ float sW[DR * DK];   // 32 KB
    __shared__ float su[H * DR];    // 8 KB
    int tid = threadIdx.x;
    int m = blockIdx.x, b = blockIdx.y;

    for (int i = tid; i < DR * DK; i += 256) sW[i] = Wrv[i];
    for (int i = tid; i < H * DR; i += 256) {
        int h = i >> 7, e = i & 127;
        su[i] = g_u[((long long)(b * H + h) * NN + m) * DR + e];
    }
    __syncthreads();

    for (int c = tid; c < DD; c += 256) {
        int h = c >> 6, d = c & 63;
        float acc = brv[d] + g_av[((long long)(b * H + h) * NN + m) * DK + d];
        const float* uu = su + h * DR;
        #pragma unroll 8
        for (int e = 0; e < DR; e++) acc += uu[e] * sW[e * DK + d];
        g_val[((long long)(b * NN + m)) * DD + c] = acc;
    }
}

// ---------------- host launcher ----------------
extern "C" void kernel_launch(void* const* d_in, const int* in_sizes, int n_in,
                              void* d_out, int out_size)
{
    const float* q   = (const float*)d_in[0];
    const float* k   = (const float*)d_in[1];
    const float* v   = (const float*)d_in[2];
    const float* r_k = (const float*)d_in[3];
    const float* r_v = (const float*)d_in[4];
    const float* Wq  = (const float*)d_in[5];
    const float* bq  = (const float*)d_in[6];
    const float* Wk  = (const float*)d_in[7];
    const float* bk  = (const float*)d_in[8];
    const float* Wv  = (const float*)d_in[9];
    const float* bv  = (const float*)d_in[10];
    const float* Wrk = (const float*)d_in[11];
    // d_in[12] = brk: per-row-constant in softmax -> drops out, unused
    const float* Wrv = (const float*)d_in[13];
    const float* brv = (const float*)d_in[14];
    const float* Wo  = (const float*)d_in[15];
    const float* bo  = (const float*)d_in[16];
    float* out = (float*)d_out;

    float *qh, *khT, *vh, *qtil, *score, *av, *val, *WrkT;
    cudaGetSymbolAddress((void**)&qh,    g_qh);
    cudaGetSymbolAddress((void**)&khT,   g_khT);
    cudaGetSymbolAddress((void**)&vh,    g_vh);
    cudaGetSymbolAddress((void**)&qtil,  g_qtil);
    cudaGetSymbolAddress((void**)&score, g_score);
    cudaGetSymbolAddress((void**)&av,    g_av);
    cudaGetSymbolAddress((void**)&val,   g_val);
    cudaGetSymbolAddress((void**)&WrkT,  g_WrkT);

    dim3 blk(256);
    const float scale = 0.125f;  // 1/sqrt(64)

    // projections: qh (HEAD), khT (HEADT), vh (HEAD)
    sgemm_k<<<dim3(8, 16, 1), blk>>>(q, Wq, bq, qh,  2048, 1024, 1024, 1.0f, 0, 0, 0, 1);
    sgemm_k<<<dim3(8, 16, 1), blk>>>(k, Wk, bk, khT, 2048, 1024, 1024, 1.0f, 0, 0, 0, 2);
    sgemm_k<<<dim3(8, 16, 1), blk>>>(v, Wv, bv, vh,  2048, 1024, 1024, 1.0f, 0, 0, 0, 1);

    // q~ = qh @ Wrk^T
    transp_wrk<<<32, 256>>>(Wrk);
    sgemm_k<<<dim3(1, 256, 1), blk>>>(qh, WrkT, nullptr, qtil,
                                      BH * NN, DR, DK, 1.0f, 0, 0, 0, 0);

    // scoreQK[bh] = scale * qh[bh] @ khT[bh]   (batched, 64 batches)
    sgemm_k<<<dim3(4, 4, BH), blk>>>(qh, khT, nullptr, score,
                                     NN, NN, DK, scale,
                                     (long long)NN * DK, (long long)DK * NN,
                                     (long long)NN * NN, 0);

    // fused bias + softmax + u
    cudaFuncSetAttribute(attn_k, cudaFuncAttributeMaxDynamicSharedMemorySize, ATTN_SMEM);
    attn_k<<<dim3(NN, BB, 1), blk, ATTN_SMEM>>>(r_k, r_v);

    // av[bh] = att[bh] @ vh[bh]   (batched, N=64 -> masked half tile)
    sgemm_k<<<dim3(1, 4, BH), blk>>>(score, vh, nullptr, av,
                                     NN, DK, NN, 1.0f,
                                     (long long)NN * NN, (long long)NN * DK,
                                     (long long)NN * DK, 0);

    // val = av + u @ Wrv + brv   (written in [B,N,D] layout)
    assemble_k<<<dim3(NN, BB, 1), blk>>>(Wrv, brv);

    // out = val @ Wo + bo
    sgemm_k<<<dim3(8, 16, 1), blk>>>(val, Wo, bo, out, 2048, 1024, 1024, 1.0f, 0, 0, 0, 0);
}

// round 4
// speedup vs baseline: 1.3245x; 1.3245x over previous
#include <cuda_runtime.h>
#include <math.h>
#include <stdint.h>

#define H   16
#define BB  4
#define NN  512
#define DD  1024
#define DK  64
#define DR  128
#define BH  (BB*H)   // 64

// ---------------- scratch (static device globals; no allocation) ----------------
__device__ float g_qh  [BH*NN*DK];        // [bh][n][d]     8 MB
__device__ float g_khT [BH*DK*NN];        // [bh][d][n]     8 MB
__device__ float g_vh  [BH*NN*DK];        // [bh][n][d]     8 MB
__device__ float g_qtil[BH*NN*DR];        // [bh][n][e]    16 MB
__device__ float g_score[BH*NN*NN];       // [bh][m][n]    64 MB (score -> att in place)
__device__ float g_u   [BH*NN*DR];        // [bh][m][e]    16 MB
__device__ float g_av  [BH*NN*DK];        // [bh][m][d]     8 MB
__device__ float g_val [BB*NN*DD];        // [b][m][h*64+d] 8 MB
__device__ float g_WrkT[DK*DR];           // [d][e]

// ---------------- tf32 helpers ----------------
__device__ __forceinline__ void split_tf32(float x, uint32_t& hi, uint32_t& lo) {
    uint32_t h;
    asm("cvt.rna.tf32.f32 %0, %1;" : "=r"(h) : "f"(x));
    float r = x - __uint_as_float(h);
    uint32_t l;
    asm("cvt.rna.tf32.f32 %0, %1;" : "=r"(l) : "f"(r));
    hi = h; lo = l;
}

__device__ __forceinline__ void mma_tf32(float* d, const uint32_t* a, const uint32_t* b) {
    asm volatile(
        "mma.sync.aligned.m16n8k8.row.col.f32.tf32.tf32.f32 "
        "{%0,%1,%2,%3}, {%4,%5,%6,%7}, {%8,%9}, {%0,%1,%2,%3};"
        : "+f"(d[0]), "+f"(d[1]), "+f"(d[2]), "+f"(d[3])
        : "r"(a[0]), "r"(a[1]), "r"(a[2]), "r"(a[3]), "r"(b[0]), "r"(b[1]));
}

// ---------------- tensor-core fp32 GEMM via 3xTF32 ----------------
// C = alpha * A@B (+bias). BM=128, BN=64, BK=16, 256 threads (8 warps, 4x2),
// warp tile 32x32 = 2x4 m16n8k8 tiles. Requires M%128==0, N%64==0, K%16==0.
// Batched via blockIdx.z with strides sA,sB,sC (elements).
// mode 0: C[z*sC + r*N + c]
// mode 1: HEAD  : [((b*16+h)*512+n)*64 + d]  where b=r>>9, n=r&511, h=c>>6, d=c&63
// mode 2: HEADT : [((b*16+h)*64+d)*512 + n]
__global__ __launch_bounds__(256) void tgemm_k(
    const float* __restrict__ A, const float* __restrict__ B,
    const float* __restrict__ bias, float* __restrict__ C,
    int M, int N, int K, float alpha,
    long long sA, long long sB, long long sC, int mode)
{
    __shared__ float As[16][136];   // [k][m], padded: frag loads conflict-free
    __shared__ float Bs[16][72];    // [k][n], padded

    const int tid  = threadIdx.x;
    const int lane = tid & 31;
    const int wid  = tid >> 5;
    const int wm = (wid >> 1) * 32;         // warp row origin within block: 0,32,64,96
    const int wn = (wid & 1) * 32;          // warp col origin within block: 0,32
    const int r0 = lane >> 2;               // 0..7
    const int c0 = lane & 3;                // 0..3

    const int rowBase = blockIdx.y * 128;
    const int colBase = blockIdx.x * 64;

    const float* Ag = A + blockIdx.z * sA;
    const float* Bg = B + blockIdx.z * sB;
    const long long zoff = blockIdx.z * sC;

    float acc[2][4][4];
    #pragma unroll
    for (int t = 0; t < 2; t++)
        #pragma unroll
        for (int u = 0; u < 4; u++)
            #pragma unroll
            for (int i = 0; i < 4; i++) acc[t][u][i] = 0.f;

    for (int k0 = 0; k0 < K; k0 += 16) {
        // --- load A tile 128x16 into As[k][m] (transposed scatter) ---
        #pragma unroll
        for (int j = 0; j < 2; j++) {
            int fidx = tid + j * 256;           // 0..511
            int arow = fidx >> 2;               // 0..127
            int ak4  = fidx & 3;                // 0..3
            float4 v = *(const float4*)(Ag + (long long)(rowBase + arow) * K + k0 + ak4 * 4);
            As[ak4 * 4 + 0][arow] = v.x;
            As[ak4 * 4 + 1][arow] = v.y;
            As[ak4 * 4 + 2][arow] = v.z;
            As[ak4 * 4 + 3][arow] = v.w;
        }
        // --- load B tile 16x64 into Bs[k][n] ---
        {
            int bk = tid >> 4;                  // 0..15
            int n  = (tid & 15) * 4;
            float4 v = *(const float4*)(Bg + (long long)(k0 + bk) * N + colBase + n);
            *(float4*)&Bs[bk][n] = v;
        }
        __syncthreads();

        #pragma unroll
        for (int ks = 0; ks < 16; ks += 8) {
            uint32_t ahi[2][4], alo[2][4], bhi[4][2], blo[4][2];
            #pragma unroll
            for (int t = 0; t < 2; t++) {
                int mb = wm + t * 16 + r0;
                split_tf32(As[ks + c0    ][mb    ], ahi[t][0], alo[t][0]);
                split_tf32(As[ks + c0    ][mb + 8], ahi[t][1], alo[t][1]);
                split_tf32(As[ks + c0 + 4][mb    ], ahi[t][2], alo[t][2]);
                split_tf32(As[ks + c0 + 4][mb + 8], ahi[t][3], alo[t][3]);
            }
            #pragma unroll
            for (int u = 0; u < 4; u++) {
                int nb = wn + u * 8 + r0;
                split_tf32(Bs[ks + c0    ][nb], bhi[u][0], blo[u][0]);
                split_tf32(Bs[ks + c0 + 4][nb], bhi[u][1], blo[u][1]);
            }
            #pragma unroll
            for (int t = 0; t < 2; t++)
                #pragma unroll
                for (int u = 0; u < 4; u++) {
                    mma_tf32(acc[t][u], alo[t], bhi[u]);
                    mma_tf32(acc[t][u], ahi[t], blo[u]);
                    mma_tf32(acc[t][u], ahi[t], bhi[u]);
                }
        }
        __syncthreads();
    }

    // --- epilogue ---
    #pragma unroll
    for (int t = 0; t < 2; t++) {
        int row0 = rowBase + wm + t * 16 + r0;
        #pragma unroll
        for (int u = 0; u < 4; u++) {
            int col0 = colBase + wn + u * 8 + c0 * 2;
            #pragma unroll
            for (int i = 0; i < 4; i++) {
                int r = row0 + (i >> 1) * 8;
                int c = col0 + (i & 1);
                float v = acc[t][u][i] * alpha;
                if (bias) v += bias[c];
                long long idx;
                if (mode == 0) {
                    idx = zoff + (long long)r * N + c;
                } else {
                    int b = r >> 9, n = r & 511, h = c >> 6, d = c & 63;
                    if (mode == 1) idx = ((long long)(b * H + h) * NN + n) * DK + d;
                    else           idx = ((long long)(b * H + h) * DK + d) * NN + n;
                }
                C[idx] = v;
            }
        }
    }
}

// ---------------- Wrk transpose: WrkT[d][e] = Wrk[e][d] ----------------
__global__ void transp_wrk(const float* __restrict__ Wrk)
{
    int i = blockIdx.x * 256 + threadIdx.x;
    if (i < DR * DK) {
        int e = i >> 6, d = i & 63;
        g_WrkT[d * DR + e] = Wrk[i];
    }
}

// ---------------- fused attention per (b, m) ----------------
#define CHUNK_PAD 132
#define ATTN_SMEM ((H*NN + H*DR + 16*CHUNK_PAD) * 4)   // 49408 B

__global__ __launch_bounds__(256) void attn_k(
    const float* __restrict__ rk, const float* __restrict__ rv)
{
    extern __shared__ float sm[];
    float* s_score = sm;                  // 16*512
    float* s_qtil  = sm + H * NN;         // 16*128
    float* s_chunk = s_qtil + H * DR;     // 16*132 (padded)

    int tid = threadIdx.x;
    int m = blockIdx.x, b = blockIdx.y;

    for (int i = tid; i < H * DR; i += 256) {
        int h = i >> 7, e = i & 127;
        s_qtil[i] = g_qtil[((long long)(b * H + h) * NN + m) * DR + e];
    }
    for (int i = tid; i < H * NN; i += 256) {
        int h = i >> 9, n = i & 511;
        s_score[i] = g_score[((long long)(b * H + h) * NN + m) * NN + n];
    }
    __syncthreads();

    // ---- phase 1: relation-key bias. score[h][n] += q~[h,:] . r_k[b,m,n,:]
    const float* rkb = rk + ((long long)(b * NN + m)) * NN * DR;
    int hh = tid >> 4, nl = tid & 15;
    for (int nc = 0; nc < NN / 16; nc++) {
        const float4* src = (const float4*)(rkb + (long long)nc * 2048);
        #pragma unroll
        for (int j = 0; j < 2; j++) {
            int g = tid + j * 256;
            int cn = g >> 5, ce = (g & 31) << 2;
            *(float4*)&s_chunk[cn * CHUNK_PAD + ce] = src[g];
        }
        __syncthreads();
        float acc = 0.f;
        const float4* q4 = (const float4*)(s_qtil + hh * DR);
        const float4* c4 = (const float4*)(s_chunk + nl * CHUNK_PAD);
        #pragma unroll
        for (int e4 = 0; e4 < DR / 4; e4++) {
            float4 a = q4[e4], r = c4[e4];
            acc += a.x * r.x + a.y * r.y + a.z * r.z + a.w * r.w;
        }
        s_score[hh * NN + nc * 16 + nl] += acc;
        __syncthreads();
    }

    // ---- phase 2: softmax per head row
    int w = tid >> 5, lane = tid & 31;
    for (int h = w * 2; h < w * 2 + 2; h++) {
        float* row = s_score + h * NN;
        float mx = -1e30f;
        for (int n = lane; n < NN; n += 32) mx = fmaxf(mx, row[n]);
        #pragma unroll
        for (int o = 16; o; o >>= 1) mx = fmaxf(mx, __shfl_xor_sync(0xffffffffu, mx, o));
        float sum = 0.f;
        for (int n = lane; n < NN; n += 32) {
            float e = __expf(row[n] - mx);
            row[n] = e;
            sum += e;
        }
        #pragma unroll
        for (int o = 16; o; o >>= 1) sum += __shfl_xor_sync(0xffffffffu, sum, o);
        float inv = 1.0f / sum;
        float* gatt = g_score + ((long long)(b * H + h) * NN + m) * NN;
        for (int n = lane; n < NN; n += 32) {
            float a = row[n] * inv;
            row[n] = a;
            gatt[n] = a;
        }
    }
    __syncthreads();

    // ---- phase 3: u[h][e] = sum_n att[h][n] * r_v[b,m,n,e]
    const float* rvb = rv + ((long long)(b * NN + m)) * NN * DR;
    int e = tid & 127, hg = tid >> 7;
    float ur[8];
    #pragma unroll
    for (int j = 0; j < 8; j++) ur[j] = 0.f;

    for (int nc = 0; nc < NN / 16; nc++) {
        const float4* src = (const float4*)(rvb + (long long)nc * 2048);
        #pragma unroll
        for (int j = 0; j < 2; j++) {
            int g = tid + j * 256;
            int cn = g >> 5, ce = (g & 31) << 2;
            *(float4*)&s_chunk[cn * CHUNK_PAD + ce] = src[g];
        }
        __syncthreads();
        #pragma unroll
        for (int nl = 0; nl < 16; nl++) {
            int n = nc * 16 + nl;
            float rvv = s_chunk[nl * CHUNK_PAD + e];
            #pragma unroll
            for (int j = 0; j < 8; j++)
                ur[j] += s_score[(hg * 8 + j) * NN + n] * rvv;
        }
        __syncthreads();
    }
    #pragma unroll
    for (int j = 0; j < 8; j++)
        g_u[((long long)(b * H + hg * 8 + j) * NN + m) * DR + e] = ur[j];
}

// ---------------- val assembly: val[b,m,h*64+d] = av + u@Wrv + brv ----------------
__global__ __launch_bounds__(256) void assemble_k(
    const float* __restrict__ Wrv, const float* __restrict__ brv)
{
    __shared__ float sW[DR * DK];   // 32 KB
    __shared__ float su[H * DR];    // 8 KB
    int tid = threadIdx.x;
    int m = blockIdx.x, b = blockIdx.y;

    for (int i = tid; i < DR * DK; i += 256) sW[i] = Wrv[i];
    for (int i = tid; i < H * DR; i += 256) {
        int h = i >> 7, e = i & 127;
        su[i] = g_u[((long long)(b * H + h) * NN + m) * DR + e];
    }
    __syncthreads();

    for (int c = tid; c < DD; c += 256) {
        int h = c >> 6, d = c & 63;
        float acc = brv[d] + g_av[((long long)(b * H + h) * NN + m) * DK + d];
        const float* uu = su + h * DR;
        #pragma unroll 8
        for (int e = 0; e < DR; e++) acc += uu[e] * sW[e * DK + d];
        g_val[((long long)(b * NN + m)) * DD + c] = acc;
    }
}

// ---------------- host launcher ----------------
extern "C" void kernel_launch(void* const* d_in, const int* in_sizes, int n_in,
                              void* d_out, int out_size)
{
    const float* q   = (const float*)d_in[0];
    const float* k   = (const float*)d_in[1];
    const float* v   = (const float*)d_in[2];
    const float* r_k = (const float*)d_in[3];
    const float* r_v = (const float*)d_in[4];
    const float* Wq  = (const float*)d_in[5];
    const float* bq  = (const float*)d_in[6];
    const float* Wk  = (const float*)d_in[7];
    const float* bk  = (const float*)d_in[8];
    const float* Wv  = (const float*)d_in[9];
    const float* bv  = (const float*)d_in[10];
    const float* Wrk = (const float*)d_in[11];
    // d_in[12] = brk: per-row-constant in softmax -> drops out, unused
    const float* Wrv = (const float*)d_in[13];
    const float* brv = (const float*)d_in[14];
    const float* Wo  = (const float*)d_in[15];
    const float* bo  = (const float*)d_in[16];
    float* out = (float*)d_out;

    float *qh, *khT, *vh, *qtil, *score, *av, *val, *WrkT;
    cudaGetSymbolAddress((void**)&qh,    g_qh);
    cudaGetSymbolAddress((void**)&khT,   g_khT);
    cudaGetSymbolAddress((void**)&vh,    g_vh);
    cudaGetSymbolAddress((void**)&qtil,  g_qtil);
    cudaGetSymbolAddress((void**)&score, g_score);
    cudaGetSymbolAddress((void**)&av,    g_av);
    cudaGetSymbolAddress((void**)&val,   g_val);
    cudaGetSymbolAddress((void**)&WrkT,  g_WrkT);

    dim3 blk(256);
    const float scale = 0.125f;  // 1/sqrt(64)

    // projections: qh (HEAD), khT (HEADT), vh (HEAD).  M=2048,N=1024,K=1024
    tgemm_k<<<dim3(16, 16, 1), blk>>>(q, Wq, bq, qh,  2048, 1024, 1024, 1.0f, 0, 0, 0, 1);
    tgemm_k<<<dim3(16, 16, 1), blk>>>(k, Wk, bk, khT, 2048, 1024, 1024, 1.0f, 0, 0, 0, 2);
    tgemm_k<<<dim3(16, 16, 1), blk>>>(v, Wv, bv, vh,  2048, 1024, 1024, 1.0f, 0, 0, 0, 1);

    // q~ = qh @ Wrk^T   M=32768, N=128, K=64
    transp_wrk<<<32, 256>>>(Wrk);
    tgemm_k<<<dim3(2, 256, 1), blk>>>(qh, WrkT, nullptr, qtil,
                                      BH * NN, DR, DK, 1.0f, 0, 0, 0, 0);

    // scoreQK[bh] = scale * qh[bh] @ khT[bh]   M=512,N=512,K=64, 64 batches
    tgemm_k<<<dim3(8, 4, BH), blk>>>(qh, khT, nullptr, score,
                                     NN, NN, DK, scale,
                                     (long long)NN * DK, (long long)DK * NN,
                                     (long long)NN * NN, 0);

    // fused bias + softmax + u
    cudaFuncSetAttribute(attn_k, cudaFuncAttributeMaxDynamicSharedMemorySize, ATTN_SMEM);
    attn_k<<<dim3(NN, BB, 1), blk, ATTN_SMEM>>>(r_k, r_v);

    // av[bh] = att[bh] @ vh[bh]   M=512,N=64,K=512, 64 batches
    tgemm_k<<<dim3(1, 4, BH), blk>>>(score, vh, nullptr, av,
                                     NN, DK, NN, 1.0f,
                                     (long long)NN * NN, (long long)NN * DK,
                                     (long long)NN * DK, 0);

    // val = av + u @ Wrv + brv   (written in [B,N,D] layout)
    assemble_k<<<dim3(NN, BB, 1), blk>>>(Wrv, brv);

    // out = val @ Wo + bo   M=2048,N=1024,K=1024
    tgemm_k<<<dim3(16, 16, 1), blk>>>(val, Wo, bo, out, 2048, 1024, 1024, 1.0f, 0, 0, 0, 0);
}